// round 14
// baseline (speedup 1.0000x reference)
#include <cuda_runtime.h>
#include <cuda_bf16.h>
#include <float.h>
#include <math.h>
#include <stdint.h>

// Problem constants
#define BB 8
#define NN 2048
#define NP (BB*NN)        // 16384 points
#define DD 64
#define KNB 8
#define LV 3
#define H1 256
#define H2 128

// Spatial grid for exact KNN
#define GC 24
#define GC3 (GC*GC*GC)        // 13824
#define GC3P 14336            // padded to 1024*14
#define GLO (-4.2f)
#define GH  (0.35f)
#define GINVH (1.0f/0.35f)

typedef __nv_bfloat16 bf16;

// ---------------- scratch (device globals; no allocation allowed) --------------
__device__ bf16   g_PQb  [NP*128];     // [16384,128] bf16; cols 0-63 P, 64-127 Q
__device__ float  g_fw   [NP*LV];
__device__ int    g_idx  [NP*KNB];
__device__ bf16   g_Bt1B [H1*192];     // Wf1^T bf16 [256][192]
__device__ bf16   g_Bt2B [H2*H1];      // Wf2^T bf16 [128][256]
__device__ float4 g_sorted[NP];        // cell-ordered points (x,y,z,idx_as_float)
__device__ int    g_cellS[BB][GC3+1];  // per-batch cell start offsets

__device__ __forceinline__ float leaky(float v){ return v > 0.f ? v : 0.2f*v; }

__device__ __forceinline__ uint32_t smem_u32(const void* p) {
    uint32_t a;
    asm("{ .reg .u64 t; cvta.to.shared.u64 t, %1; cvt.u32.u64 %0, t; }" : "=r"(a) : "l"(p));
    return a;
}

#define CP_ASYNC16(d, s) do { \
    size_t _gs = __cvta_generic_to_global(s); \
    asm volatile("cp.async.cg.shared.global [%0], [%1], 16;" :: "r"(d), "l"(_gs) : "memory"); \
} while (0)
#define CP_COMMIT()  asm volatile("cp.async.commit_group;" ::: "memory")
#define CP_WAIT(n)   asm volatile("cp.async.wait_group %0;" :: "n"(n) : "memory")

__device__ __forceinline__ void mma_bf16(float* c, const uint32_t* a, const uint32_t* b) {
    asm volatile(
        "mma.sync.aligned.m16n8k16.row.col.f32.bf16.bf16.f32 "
        "{%0,%1,%2,%3}, {%4,%5,%6,%7}, {%8,%9}, {%0,%1,%2,%3};"
        : "+f"(c[0]), "+f"(c[1]), "+f"(c[2]), "+f"(c[3])
        : "r"(a[0]), "r"(a[1]), "r"(a[2]), "r"(a[3]), "r"(b[0]), "r"(b[1]));
}

__device__ __forceinline__ float bf2f(uint32_t u, int hi) {
    __nv_bfloat162 v = *(__nv_bfloat162*)&u;
    return hi ? __bfloat162float(v.y) : __bfloat162float(v.x);
}

// ================= kernel 0: grid build (counting sort per batch) ==============
#define GRID_SMEM ((GC3P + 32)*4)   // 57472 bytes

__global__ void __launch_bounds__(1024)
k_grid(const float* __restrict__ x)
{
    extern __shared__ int gsm[];
    int* cnt  = gsm;            // [GC3P]
    int* wsum = gsm + GC3P;     // [32]
    const int b = blockIdx.x, tid = threadIdx.x;
    const int lane = tid & 31, wid = tid >> 5;

    for (int i = tid; i < GC3P; i += 1024) cnt[i] = 0;
    __syncthreads();

    float px[2], py[2], pz[2]; int pc[2];
    #pragma unroll
    for (int r = 0; r < 2; r++) {
        int o = r*1024 + tid;
        int p = b*NN + o;
        float a = x[p*3+0], c = x[p*3+1], e = x[p*3+2];
        px[r] = a; py[r] = c; pz[r] = e;
        int ix = min(GC-1, max(0, (int)floorf((a - GLO)*GINVH)));
        int iy = min(GC-1, max(0, (int)floorf((c - GLO)*GINVH)));
        int iz = min(GC-1, max(0, (int)floorf((e - GLO)*GINVH)));
        pc[r] = (iz*GC + iy)*GC + ix;
        atomicAdd(&cnt[pc[r]], 1);
    }
    __syncthreads();

    // exclusive scan over GC3P cells: 14 per thread + block scan
    const int base = tid*14;
    int loc[14]; int s = 0;
    #pragma unroll
    for (int k = 0; k < 14; k++) { loc[k] = s; s += cnt[base + k]; }
    int inc = s;
    #pragma unroll
    for (int o = 1; o < 32; o <<= 1) {
        int v = __shfl_up_sync(0xFFFFFFFFu, inc, o);
        if (lane >= o) inc += v;
    }
    if (lane == 31) wsum[wid] = inc;
    int exw = inc - s;
    __syncthreads();
    if (wid == 0) {
        int v = wsum[lane];
        int iv = v;
        #pragma unroll
        for (int o = 1; o < 32; o <<= 1) {
            int t2 = __shfl_up_sync(0xFFFFFFFFu, iv, o);
            if (lane >= o) iv += t2;
        }
        wsum[lane] = iv - v;
    }
    __syncthreads();
    const int tbase = exw + wsum[wid];
    #pragma unroll
    for (int k = 0; k < 14; k++) {
        int c = base + k;
        int st = tbase + loc[k];
        cnt[c] = st;
        if (c < GC3) g_cellS[b][c] = st;
    }
    if (tid == 0) g_cellS[b][GC3] = NN;
    __syncthreads();

    #pragma unroll
    for (int r = 0; r < 2; r++) {
        int pos = atomicAdd(&cnt[pc[r]], 1);
        int orig = r*1024 + tid;
        g_sorted[b*NN + pos] = make_float4(px[r], py[r], pz[r], __int_as_float(orig));
    }
}

// ================ kernel 1 (front): grid-KNN || feature+PQ GEMM || prep ========
// 512-thread blocks, 2 resident/SM.
// blocks [0,32):    grid KNN, 1 query/thread (512 q/block, 4 blocks/batch)
// blocks [32,160):  feature+suppressor+PQ mma, 128 points/block (2 tiles)
// blocks [160,184): Wf1/Wf2 transposes to bf16
#define BSRQ 36
#define ASRQ 36
#define KNN_BYTES (NN*16 + (GC3+1)*4)            // 32768 + 55300 = 88068
#define FRONT_SMEM 88320

__global__ void __launch_bounds__(512, 2)
k_front(const float* __restrict__ x,
        const float* __restrict__ W1, const float* __restrict__ b1,
        const float* __restrict__ g1, const float* __restrict__ be1,
        const float* __restrict__ Ws1, const float* __restrict__ bs1,
        const float* __restrict__ Ws2, const float* __restrict__ bs2,
        const float* __restrict__ W2, const float* __restrict__ Wf1,
        const float* __restrict__ Wf2)
{
    extern __shared__ char fsm[];
    const int bx = blockIdx.x;
    const int tid = threadIdx.x;

    if (bx >= 160) {                 // ---- weight prep ----
        int base = (bx - 160)*2048;
        for (int i = base + tid; i < base + 2048; i += 512) {
            if (i < H1*192) { int n = i/192, k = i%192; g_Bt1B[i] = __float2bfloat16_rn(Wf1[k*H1 + n]); }
            if (i < H2*H1)  { int n = i>>8,  k = i&255; g_Bt2B[i] = __float2bfloat16_rn(Wf2[k*H2 + n]); }
        }
        return;
    }

    if (bx >= 32) {                  // ---- feature + suppressor + PQ GEMM ----
        uint32_t* sB = (uint32_t*)fsm;                 // Btpq [128][64bf16]
        uint32_t* sAall = (uint32_t*)fsm + 128*BSRQ;   // 2 tiles x [64][64]

        const int tile = tid >> 8;        // 0..1
        const int t256 = tid & 255;
        const int m0 = (bx - 32)*128 + tile*64;

        bf16* sBh = (bf16*)sB;
        for (int i = tid; i < 128*64; i += 512) {
            int k = i >> 7, n = i & 127;
            float w = (n < 64) ? W2[k*DD + n] : W2[(64 + k)*DD + (n - 64)];
            sBh[n*(2*BSRQ) + k] = __float2bfloat16_rn(w);
        }

        const int pt = t256 >> 2, q = t256 & 3, d0 = q*16;
        const int p = m0 + pt;
        float x0 = x[p*3+0], x1 = x[p*3+1], x2 = x[p*3+2];
        float s0 = 0.f, s1 = 0.f, s2 = 0.f;
        bf16* sAh = (bf16*)(sAall + tile*64*ASRQ);
        #pragma unroll
        for (int j = 0; j < 16; j++) {
            int d = d0 + j;
            float f = x0*W1[d] + x1*W1[DD+d] + x2*W1[2*DD+d] + b1[d];
            f = leaky(f*g1[d] + be1[d]);
            sAh[pt*(2*ASRQ) + d] = __float2bfloat16_rn(f);
            float hh = x0*Ws1[d] + x1*Ws1[DD+d] + x2*Ws1[2*DD+d] + bs1[d];
            hh = hh > 0.f ? hh : 0.f;
            s0 += hh*Ws2[d*LV+0]; s1 += hh*Ws2[d*LV+1]; s2 += hh*Ws2[d*LV+2];
        }
        s0 += __shfl_xor_sync(0xFFFFFFFF, s0, 1); s0 += __shfl_xor_sync(0xFFFFFFFF, s0, 2);
        s1 += __shfl_xor_sync(0xFFFFFFFF, s1, 1); s1 += __shfl_xor_sync(0xFFFFFFFF, s1, 2);
        s2 += __shfl_xor_sync(0xFFFFFFFF, s2, 1); s2 += __shfl_xor_sync(0xFFFFFFFF, s2, 2);
        if (q == 0) {
            g_fw[p*LV+0] = 1.f/(1.f + expf(-s0));
            g_fw[p*LV+1] = 1.f/(1.f + expf(-s1));
            g_fw[p*LV+2] = 1.f/(1.f + expf(-s2));
        }
        __syncthreads();

        const int w8 = (tid >> 5) & 7;
        const int lane = tid & 31, gid = lane >> 2, tig = lane & 3;
        const int wm = (w8 & 1)*32, wn = (w8 >> 1)*32;
        const uint32_t* sA = sAall + tile*64*ASRQ;
        float acc[2][4][4] = {};
        #pragma unroll
        for (int ks = 0; ks < 4; ks++) {
            const int ko = ks*8;
            uint32_t af[2][4], bfr[4][2];
            #pragma unroll
            for (int mf = 0; mf < 2; mf++) {
                const uint32_t* ap = sA + (wm + mf*16 + gid)*ASRQ + ko + tig;
                af[mf][0] = ap[0];
                af[mf][1] = ap[8*ASRQ];
                af[mf][2] = ap[4];
                af[mf][3] = ap[8*ASRQ + 4];
            }
            #pragma unroll
            for (int nf = 0; nf < 4; nf++) {
                const uint32_t* bp = sB + (wn + nf*8 + gid)*BSRQ + ko + tig;
                bfr[nf][0] = bp[0];
                bfr[nf][1] = bp[4];
            }
            #pragma unroll
            for (int mf = 0; mf < 2; mf++)
                #pragma unroll
                for (int nf = 0; nf < 4; nf++)
                    mma_bf16(acc[mf][nf], af[mf], bfr[nf]);
        }
        #pragma unroll
        for (int mf = 0; mf < 2; mf++) {
            const int row = m0 + wm + mf*16 + gid;
            #pragma unroll
            for (int nf = 0; nf < 4; nf++) {
                const int col = wn + nf*8 + tig*2;
                __nv_bfloat162 lo, hi;
                lo.x = __float2bfloat16_rn(acc[mf][nf][0]); lo.y = __float2bfloat16_rn(acc[mf][nf][1]);
                hi.x = __float2bfloat16_rn(acc[mf][nf][2]); hi.y = __float2bfloat16_rn(acc[mf][nf][3]);
                *(__nv_bfloat162*)(g_PQb + (size_t)row*128 + col)     = lo;
                *(__nv_bfloat162*)(g_PQb + (size_t)(row+8)*128 + col) = hi;
            }
        }
        return;
    }

    // ---- grid KNN: 1 query/thread, exact expanding-ring search ----
    {
        float4* sS  = (float4*)fsm;               // sorted points [2048]
        int*    sSt = (int*)(fsm + NN*16);        // cell starts [GC3+1]
        const int b = bx >> 2;                    // 4 blocks per batch

        for (int i = tid; i < NN; i += 512) sS[i] = g_sorted[b*NN + i];
        for (int i = tid; i < GC3+1; i += 512) sSt[i] = g_cellS[b][i];
        __syncthreads();

        const int p = bx*512 + tid;               // global query id
        const float qx = x[p*3+0], qy = x[p*3+1], qz = x[p*3+2];
        const int cx = min(GC-1, max(0, (int)floorf((qx - GLO)*GINVH)));
        const int cy = min(GC-1, max(0, (int)floorf((qy - GLO)*GINVH)));
        const int cz = min(GC-1, max(0, (int)floorf((qz - GLO)*GINVH)));

        float bd[KNB]; int bi[KNB];
        #pragma unroll
        for (int t2 = 0; t2 < KNB; t2++) { bd[t2] = FLT_MAX; bi[t2] = 0; }

        for (int c = 0; c < GC; c++) {
            int zl = max(cz - c, 0), zh = min(cz + c, GC-1);
            int yl = max(cy - c, 0), yh = min(cy + c, GC-1);
            int xl = max(cx - c, 0), xh = min(cx + c, GC-1);
            for (int zz = zl; zz <= zh; zz++) {
                bool zf = (zz == cz - c) || (zz == cz + c);
                for (int yy = yl; yy <= yh; yy++) {
                    bool yf = (yy == cy - c) || (yy == cy + c);
                    int rowBase = (zz*GC + yy)*GC;
                    if (zf || yf) {
                        // full x-span of this row (cells contiguous in memory)
                        int s = sSt[rowBase + xl], e = sSt[rowBase + xh + 1];
                        for (int j = s; j < e; j++) {
                            float4 pt = sS[j];
                            float ddx = qx - pt.x, ddy = qy - pt.y, ddz = qz - pt.z;
                            float d2 = fmaf(ddx, ddx, fmaf(ddy, ddy, ddz*ddz));
                            if (d2 < bd[KNB-1]) {
                                bd[KNB-1] = d2; bi[KNB-1] = __float_as_int(pt.w);
                                #pragma unroll
                                for (int t2 = KNB-1; t2 > 0; t2--) {
                                    if (bd[t2] < bd[t2-1]) {
                                        float td = bd[t2]; bd[t2] = bd[t2-1]; bd[t2-1] = td;
                                        int   ti = bi[t2]; bi[t2] = bi[t2-1]; bi[t2-1] = ti;
                                    }
                                }
                            }
                        }
                    } else {
                        // only the two x-faces
                        #pragma unroll
                        for (int side = 0; side < 2; side++) {
                            int xxp = side ? (cx + c) : (cx - c);
                            if (xxp < 0 || xxp > GC-1) continue;
                            if (side == 1 && c == 0) continue;
                            int s = sSt[rowBase + xxp], e = sSt[rowBase + xxp + 1];
                            for (int j = s; j < e; j++) {
                                float4 pt = sS[j];
                                float ddx = qx - pt.x, ddy = qy - pt.y, ddz = qz - pt.z;
                                float d2 = fmaf(ddx, ddx, fmaf(ddy, ddy, ddz*ddz));
                                if (d2 < bd[KNB-1]) {
                                    bd[KNB-1] = d2; bi[KNB-1] = __float_as_int(pt.w);
                                    #pragma unroll
                                    for (int t2 = KNB-1; t2 > 0; t2--) {
                                        if (bd[t2] < bd[t2-1]) {
                                            float td = bd[t2]; bd[t2] = bd[t2-1]; bd[t2-1] = td;
                                            int   ti = bi[t2]; bi[t2] = bi[t2-1]; bi[t2-1] = ti;
                                        }
                                    }
                                }
                            }
                        }
                    }
                }
            }
            // termination: min distance to any unscanned cell (clamped sides exhausted)
            float dmin = FLT_MAX;
            if (cx - c > 0)    dmin = fminf(dmin, qx - (GLO + (cx - c)*GH));
            if (cx + c < GC-1) dmin = fminf(dmin, (GLO + (cx + c + 1)*GH) - qx);
            if (cy - c > 0)    dmin = fminf(dmin, qy - (GLO + (cy - c)*GH));
            if (cy + c < GC-1) dmin = fminf(dmin, (GLO + (cy + c + 1)*GH) - qy);
            if (cz - c > 0)    dmin = fminf(dmin, qz - (GLO + (cz - c)*GH));
            if (cz + c < GC-1) dmin = fminf(dmin, (GLO + (cz + c + 1)*GH) - qz);
            if (dmin == FLT_MAX || bd[KNB-1] <= dmin*dmin) break;
        }

        #pragma unroll
        for (int t2 = 0; t2 < KNB; t2++) g_idx[p*KNB + t2] = bi[t2];
    }
}

// ================= kernel 2 (tail): gather + GEMM1 + GEMM2 + out ==============
#define T_ASR 100
#define T_G1SR 132
#define T_A1 0
#define T_B1 12800
#define T_G1 38400
#define T_SMEM (55296*4)   // 221184 bytes

__global__ void __launch_bounds__(512)
k_tail(const float* __restrict__ b2, const float* __restrict__ g2,
       const float* __restrict__ be2,
       const float* __restrict__ bf1, const float* __restrict__ gf1,
       const float* __restrict__ bef1,
       const float* __restrict__ bf2, const float* __restrict__ gf2,
       const float* __restrict__ bef2,
       float* __restrict__ out, const float* __restrict__ x,
       const float* __restrict__ Wf3, const float* __restrict__ bf3)
{
    extern __shared__ uint32_t sm32[];
    __shared__ float sAcc[128][3];

    const int t = threadIdx.x, lane = t & 31, wid = t >> 5;
    const int gid = lane >> 2, tig = lane & 3;
    const int m0 = blockIdx.x * 128;
    const uint32_t sbase = smem_u32(sm32);

    #pragma unroll
    for (int it = 0; it < 12; it++) {
        int i = it*512 + t;
        int row = i/24, seg = i%24;
        CP_ASYNC16(sbase + (uint32_t)(T_B1*4 + row*400 + seg*16),
                   g_Bt1B + (size_t)row*192 + seg*8);
    }
    CP_COMMIT();

    {
        const int pt = t >> 2, q = t & 3, d0 = q*16;
        const int p = m0 + pt, b = p >> 11;

        float pv[16], gg[16], cc[16], m[16];
        uint4 pv0 = *(const uint4*)(g_PQb + (size_t)p*128 + d0);
        uint4 pv1 = *(const uint4*)(g_PQb + (size_t)p*128 + d0 + 8);
        #pragma unroll
        for (int j = 0; j < 8; j++) {
            pv[j]   = bf2f(((const uint32_t*)&pv0)[j>>1], j&1);
            pv[8+j] = bf2f(((const uint32_t*)&pv1)[j>>1], j&1);
        }
        #pragma unroll
        for (int j = 0; j < 16; j++) {
            gg[j] = g2[d0+j];
            cc[j] = b2[d0+j]*gg[j] + be2[d0+j];
            m[j] = -FLT_MAX;
        }
        int idx[KNB];
        *(int4*)&idx[0] = *(const int4*)(g_idx + p*KNB);
        *(int4*)&idx[4] = *(const int4*)(g_idx + p*KNB + 4);
        #pragma unroll
        for (int k = 0; k < KNB; k++) {
            const bf16* qrow = g_PQb + (size_t)(b*NN + idx[k])*128 + 64 + d0;
            uint4 qv0 = *(const uint4*)(qrow);
            uint4 qv1 = *(const uint4*)(qrow + 8);
            #pragma unroll
            for (int j = 0; j < 8; j++) {
                float qa = bf2f(((const uint32_t*)&qv0)[j>>1], j&1);
                float qb = bf2f(((const uint32_t*)&qv1)[j>>1], j&1);
                m[j]   = fmaxf(m[j],   leaky((pv[j]   + qa)*gg[j]   + cc[j]));
                m[8+j] = fmaxf(m[8+j], leaky((pv[8+j] + qb)*gg[8+j] + cc[8+j]));
            }
        }
        float f0 = g_fw[p*LV+0], f1 = g_fw[p*LV+1], f2 = g_fw[p*LV+2];
        bf16* sAh = (bf16*)(sm32 + T_A1);
        #pragma unroll
        for (int j = 0; j < 16; j++) {
            int d = d0 + j;
            sAh[pt*(2*T_ASR) + d]       = __float2bfloat16_rn(m[j]*f0);
            sAh[pt*(2*T_ASR) + 64 + d]  = __float2bfloat16_rn(m[j]*f1);
            sAh[pt*(2*T_ASR) + 128 + d] = __float2bfloat16_rn(m[j]*f2);
        }
    }
    if (t < 384) sAcc[t/3][t%3] = 0.f;
    CP_WAIT(0);
    __syncthreads();

    const int wm = (wid & 3)*32;
    {
        const int wn1 = (wid >> 2)*64;
        float acc1[2][8][4] = {};
        #pragma unroll
        for (int ks = 0; ks < 12; ks++) {
            const int ko = ks*8;
            uint32_t af[2][4], bfr[8][2];
            #pragma unroll
            for (int mf = 0; mf < 2; mf++) {
                const uint32_t* ap = sm32 + T_A1 + (wm + mf*16 + gid)*T_ASR + ko + tig;
                af[mf][0] = ap[0];
                af[mf][1] = ap[8*T_ASR];
                af[mf][2] = ap[4];
                af[mf][3] = ap[8*T_ASR + 4];
            }
            #pragma unroll
            for (int nf = 0; nf < 8; nf++) {
                const uint32_t* bp = sm32 + T_B1 + (wn1 + nf*8 + gid)*T_ASR + ko + tig;
                bfr[nf][0] = bp[0];
                bfr[nf][1] = bp[4];
            }
            #pragma unroll
            for (int mf = 0; mf < 2; mf++)
                #pragma unroll
                for (int nf = 0; nf < 8; nf++)
                    mma_bf16(acc1[mf][nf], af[mf], bfr[nf]);
        }
        #pragma unroll
        for (int mf = 0; mf < 2; mf++) {
            const int rl = wm + mf*16 + gid;
            #pragma unroll
            for (int nf = 0; nf < 8; nf++) {
                const int col = wn1 + nf*8 + tig*2;
                float e0 = __ldg(bf1+col),  e1 = __ldg(bf1+col+1);
                float q0 = __ldg(gf1+col),  q1 = __ldg(gf1+col+1);
                float h0 = __ldg(bef1+col), h1 = __ldg(bef1+col+1);
                float v0 = leaky((acc1[mf][nf][0] + e0)*q0 + h0);
                float v1 = leaky((acc1[mf][nf][1] + e1)*q1 + h1);
                float v2 = leaky((acc1[mf][nf][2] + e0)*q0 + h0);
                float v3 = leaky((acc1[mf][nf][3] + e1)*q1 + h1);
                __nv_bfloat162 lo, hi;
                lo.x = __float2bfloat16_rn(v0); lo.y = __float2bfloat16_rn(v1);
                hi.x = __float2bfloat16_rn(v2); hi.y = __float2bfloat16_rn(v3);
                sm32[T_G1 + rl*T_G1SR + (col>>1)]     = *(uint32_t*)&lo;
                sm32[T_G1 + (rl+8)*T_G1SR + (col>>1)] = *(uint32_t*)&hi;
            }
        }
    }
    __syncthreads();

    #pragma unroll
    for (int it = 0; it < 8; it++) {
        int i = it*512 + t;
        int row = i >> 5, seg = i & 31;
        CP_ASYNC16(sbase + (uint32_t)(T_B1*4 + row*528 + seg*16),
                   g_Bt2B + (size_t)row*256 + seg*8);
    }
    CP_COMMIT();
    CP_WAIT(0);
    __syncthreads();

    {
        const int wn2 = (wid >> 2)*32;
        float acc2[2][4][4] = {};
        #pragma unroll
        for (int ks = 0; ks < 16; ks++) {
            const int ko = ks*8;
            uint32_t af[2][4], bfr[4][2];
            #pragma unroll
            for (int mf = 0; mf < 2; mf++) {
                const uint32_t* ap = sm32 + T_G1 + (wm + mf*16 + gid)*T_G1SR + ko + tig;
                af[mf][0] = ap[0];
                af[mf][1] = ap[8*T_G1SR];
                af[mf][2] = ap[4];
                af[mf][3] = ap[8*T_G1SR + 4];
            }
            #pragma unroll
            for (int nf = 0; nf < 4; nf++) {
                const uint32_t* bp = sm32 + T_B1 + (wn2 + nf*8 + gid)*T_G1SR + ko + tig;
                bfr[nf][0] = bp[0];
                bfr[nf][1] = bp[4];
            }
            #pragma unroll
            for (int mf = 0; mf < 2; mf++)
                #pragma unroll
                for (int nf = 0; nf < 4; nf++)
                    mma_bf16(acc2[mf][nf], af[mf], bfr[nf]);
        }

        #pragma unroll
        for (int mf = 0; mf < 2; mf++) {
            float sLo[3] = {0.f,0.f,0.f}, sHi[3] = {0.f,0.f,0.f};
            #pragma unroll
            for (int nf = 0; nf < 4; nf++) {
                const int col = wn2 + nf*8 + tig*2;
                float e0 = __ldg(bf2+col),  e1 = __ldg(bf2+col+1);
                float q0 = __ldg(gf2+col),  q1 = __ldg(gf2+col+1);
                float h0 = __ldg(bef2+col), h1 = __ldg(bef2+col+1);
                float v0 = leaky((acc2[mf][nf][0] + e0)*q0 + h0);
                float v1 = leaky((acc2[mf][nf][1] + e1)*q1 + h1);
                float v2 = leaky((acc2[mf][nf][2] + e0)*q0 + h0);
                float v3 = leaky((acc2[mf][nf][3] + e1)*q1 + h1);
                #pragma unroll
                for (int j = 0; j < 3; j++) {
                    float w0 = __ldg(Wf3 + col*3 + j);
                    float w1 = __ldg(Wf3 + (col+1)*3 + j);
                    sLo[j] += v0*w0 + v1*w1;
                    sHi[j] += v2*w0 + v3*w1;
                }
            }
            #pragma unroll
            for (int j = 0; j < 3; j++) {
                sLo[j] += __shfl_xor_sync(0xFFFFFFFF, sLo[j], 1);
                sLo[j] += __shfl_xor_sync(0xFFFFFFFF, sLo[j], 2);
                sHi[j] += __shfl_xor_sync(0xFFFFFFFF, sHi[j], 1);
                sHi[j] += __shfl_xor_sync(0xFFFFFFFF, sHi[j], 2);
            }
            if (tig == 0) {
                int rl = wm + mf*16 + gid;
                #pragma unroll
                for (int j = 0; j < 3; j++) {
                    atomicAdd(&sAcc[rl][j],     sLo[j]);
                    atomicAdd(&sAcc[rl + 8][j], sHi[j]);
                }
            }
        }
    }

    __syncthreads();
    if (t < 128) {
        int p = m0 + t;
        #pragma unroll
        for (int j = 0; j < 3; j++)
            out[p*3+j] = x[p*3+j] + 0.1f*(sAcc[t][j] + __ldg(bf3+j));
    }
}

// ---------------- launch -------------------------------------------------------
extern "C" void kernel_launch(void* const* d_in, const int* in_sizes, int n_in,
                              void* d_out, int out_size)
{
    const float* x   = (const float*)d_in[0];
    const float* W1  = (const float*)d_in[1];
    const float* b1  = (const float*)d_in[2];
    const float* g1  = (const float*)d_in[3];
    const float* be1 = (const float*)d_in[4];
    const float* W2  = (const float*)d_in[5];
    const float* b2  = (const float*)d_in[6];
    const float* g2  = (const float*)d_in[7];
    const float* be2 = (const float*)d_in[8];
    const float* Ws1 = (const float*)d_in[9];
    const float* bs1 = (const float*)d_in[10];
    const float* Ws2 = (const float*)d_in[11];
    const float* bs2 = (const float*)d_in[12];
    const float* Wf1 = (const float*)d_in[13];
    const float* bf1 = (const float*)d_in[14];
    const float* gf1 = (const float*)d_in[15];
    const float* bef1= (const float*)d_in[16];
    const float* Wf2 = (const float*)d_in[17];
    const float* bf2 = (const float*)d_in[18];
    const float* gf2 = (const float*)d_in[19];
    const float* bef2= (const float*)d_in[20];
    const float* Wf3 = (const float*)d_in[21];
    const float* bf3 = (const float*)d_in[22];
    float* out = (float*)d_out;

    cudaFuncSetAttribute(k_grid,  cudaFuncAttributeMaxDynamicSharedMemorySize, GRID_SMEM);
    cudaFuncSetAttribute(k_front, cudaFuncAttributeMaxDynamicSharedMemorySize, FRONT_SMEM);
    cudaFuncSetAttribute(k_tail,  cudaFuncAttributeMaxDynamicSharedMemorySize, T_SMEM);

    // 0. spatial grid build (counting sort per batch)
    k_grid<<<BB, 1024, GRID_SMEM>>>(x);

    // 1. grid-KNN (32 blk) || feature+PQ (128 blk) || weight prep (24 blk)
    k_front<<<32 + 128 + 24, 512, FRONT_SMEM>>>(
        x, W1, b1, g1, be1, Ws1, bs1, Ws2, bs2, W2, Wf1, Wf2);

    // 2. gather + fusion1 + fusion2 + projection + residual, fully fused
    k_tail<<<NP/128, 512, T_SMEM>>>(b2, g2, be2, bf1, gf1, bef1,
                                    bf2, gf2, bef2, out, x, Wf3, bf3);
}

// round 15
// speedup vs baseline: 2.1117x; 2.1117x over previous
#include <cuda_runtime.h>
#include <cuda_bf16.h>
#include <float.h>
#include <math.h>
#include <stdint.h>

// Problem constants
#define BB 8
#define NN 2048
#define NP (BB*NN)        // 16384 points
#define DD 64
#define KNB 8
#define LV 3
#define H1 256
#define H2 128

// Spatial sort grid (order only — correctness never depends on it)
#define GC 16
#define GC3 (GC*GC*GC)        // 4096
#define GLO (-4.4f)
#define GH  (0.55f)
#define GINVH (1.0f/0.55f)

typedef __nv_bfloat16 bf16;

// ---------------- scratch (device globals; no allocation allowed) --------------
__device__ bf16   g_PQb  [NP*128];     // [16384,128] bf16; cols 0-63 P, 64-127 Q
__device__ float  g_fw   [NP*LV];
__device__ int    g_idx  [NP*KNB];
__device__ bf16   g_Bt1B [H1*192];     // Wf1^T bf16 [256][192]
__device__ bf16   g_Bt2B [H2*H1];      // Wf2^T bf16 [128][256]
__device__ float4 g_sorted[NP];        // cell-ordered (x,y,z, 0.5*norm2)
__device__ int    g_sid  [NP];         // original index of sorted point

__device__ __forceinline__ float leaky(float v){ return v > 0.f ? v : 0.2f*v; }

__device__ __forceinline__ uint32_t smem_u32(const void* p) {
    uint32_t a;
    asm("{ .reg .u64 t; cvta.to.shared.u64 t, %1; cvt.u32.u64 %0, t; }" : "=r"(a) : "l"(p));
    return a;
}

#define CP_ASYNC16(d, s) do { \
    size_t _gs = __cvta_generic_to_global(s); \
    asm volatile("cp.async.cg.shared.global [%0], [%1], 16;" :: "r"(d), "l"(_gs) : "memory"); \
} while (0)
#define CP_COMMIT()  asm volatile("cp.async.commit_group;" ::: "memory")
#define CP_WAIT(n)   asm volatile("cp.async.wait_group %0;" :: "n"(n) : "memory")

__device__ __forceinline__ void mma_bf16(float* c, const uint32_t* a, const uint32_t* b) {
    asm volatile(
        "mma.sync.aligned.m16n8k16.row.col.f32.bf16.bf16.f32 "
        "{%0,%1,%2,%3}, {%4,%5,%6,%7}, {%8,%9}, {%0,%1,%2,%3};"
        : "+f"(c[0]), "+f"(c[1]), "+f"(c[2]), "+f"(c[3])
        : "r"(a[0]), "r"(a[1]), "r"(a[2]), "r"(a[3]), "r"(b[0]), "r"(b[1]));
}

__device__ __forceinline__ float bf2f(uint32_t u, int hi) {
    __nv_bfloat162 v = *(__nv_bfloat162*)&u;
    return hi ? __bfloat162float(v.y) : __bfloat162float(v.x);
}

// ================= kernel 0: counting sort into cell order (per batch) =========
__global__ void __launch_bounds__(1024)
k_grid(const float* __restrict__ x)
{
    __shared__ int cnt[GC3];
    __shared__ int wsum[32];
    const int b = blockIdx.x, tid = threadIdx.x;
    const int lane = tid & 31, wid = tid >> 5;

    #pragma unroll
    for (int k = 0; k < 4; k++) cnt[k*1024 + tid] = 0;
    __syncthreads();

    float px[2], py[2], pz[2]; int pc[2];
    #pragma unroll
    for (int r = 0; r < 2; r++) {
        int o = r*1024 + tid;
        int p = b*NN + o;
        float a = x[p*3+0], c = x[p*3+1], e = x[p*3+2];
        px[r] = a; py[r] = c; pz[r] = e;
        int ix = min(GC-1, max(0, (int)floorf((a - GLO)*GINVH)));
        int iy = min(GC-1, max(0, (int)floorf((c - GLO)*GINVH)));
        int iz = min(GC-1, max(0, (int)floorf((e - GLO)*GINVH)));
        pc[r] = (iz*GC + iy)*GC + ix;
        atomicAdd(&cnt[pc[r]], 1);
    }
    __syncthreads();

    // exclusive scan over 4096 cells: 4/thread + warp + block scan
    const int base = tid*4;
    int loc[4]; int s = 0;
    #pragma unroll
    for (int k = 0; k < 4; k++) { loc[k] = s; s += cnt[base + k]; }
    int inc = s;
    #pragma unroll
    for (int o = 1; o < 32; o <<= 1) {
        int v = __shfl_up_sync(0xFFFFFFFFu, inc, o);
        if (lane >= o) inc += v;
    }
    if (lane == 31) wsum[wid] = inc;
    int exw = inc - s;
    __syncthreads();
    if (wid == 0) {
        int v = wsum[lane];
        int iv = v;
        #pragma unroll
        for (int o = 1; o < 32; o <<= 1) {
            int t2 = __shfl_up_sync(0xFFFFFFFFu, iv, o);
            if (lane >= o) iv += t2;
        }
        wsum[lane] = iv - v;
    }
    __syncthreads();
    const int tbase = exw + wsum[wid];
    #pragma unroll
    for (int k = 0; k < 4; k++) cnt[base + k] = tbase + loc[k];
    __syncthreads();

    #pragma unroll
    for (int r = 0; r < 2; r++) {
        int pos = atomicAdd(&cnt[pc[r]], 1);
        int orig = r*1024 + tid;
        float hn = 0.5f*(px[r]*px[r] + py[r]*py[r] + pz[r]*pz[r]);
        g_sorted[b*NN + pos] = make_float4(px[r], py[r], pz[r], hn);
        g_sid[b*NN + pos] = orig;
    }
}

// ================ kernel 1 (front): sorted-KNN || feature+PQ GEMM || prep ======
// 512-thread blocks, 2 resident/SM.
// blocks [0,32):    KNN, 4 sorted-adjacent queries/warp, circular sorted scan
// blocks [32,160):  feature+suppressor+PQ mma, 128 points/block (2 tiles)
// blocks [160,184): Wf1/Wf2 transposes to bf16
#define BSRQ 36
#define ASRQ 36
#define FRONT_SMEM 40960     // KNN: 2048*16 + 2048*4 = 40960; ppq: 36864

__global__ void __launch_bounds__(512, 2)
k_front(const float* __restrict__ x,
        const float* __restrict__ W1, const float* __restrict__ b1,
        const float* __restrict__ g1, const float* __restrict__ be1,
        const float* __restrict__ Ws1, const float* __restrict__ bs1,
        const float* __restrict__ Ws2, const float* __restrict__ bs2,
        const float* __restrict__ W2, const float* __restrict__ Wf1,
        const float* __restrict__ Wf2)
{
    extern __shared__ char fsm[];
    const int bx = blockIdx.x;
    const int tid = threadIdx.x;

    if (bx >= 160) {                 // ---- weight prep ----
        int base = (bx - 160)*2048;
        for (int i = base + tid; i < base + 2048; i += 512) {
            if (i < H1*192) { int n = i/192, k = i%192; g_Bt1B[i] = __float2bfloat16_rn(Wf1[k*H1 + n]); }
            if (i < H2*H1)  { int n = i>>8,  k = i&255; g_Bt2B[i] = __float2bfloat16_rn(Wf2[k*H2 + n]); }
        }
        return;
    }

    if (bx >= 32) {                  // ---- feature + suppressor + PQ GEMM ----
        uint32_t* sB = (uint32_t*)fsm;                 // Btpq [128][64bf16]
        uint32_t* sAall = (uint32_t*)fsm + 128*BSRQ;   // 2 tiles x [64][64]

        const int tile = tid >> 8;        // 0..1
        const int t256 = tid & 255;
        const int m0 = (bx - 32)*128 + tile*64;

        bf16* sBh = (bf16*)sB;
        for (int i = tid; i < 128*64; i += 512) {
            int k = i >> 7, n = i & 127;
            float w = (n < 64) ? W2[k*DD + n] : W2[(64 + k)*DD + (n - 64)];
            sBh[n*(2*BSRQ) + k] = __float2bfloat16_rn(w);
        }

        const int pt = t256 >> 2, q = t256 & 3, d0 = q*16;
        const int p = m0 + pt;
        float x0 = x[p*3+0], x1 = x[p*3+1], x2 = x[p*3+2];
        float s0 = 0.f, s1 = 0.f, s2 = 0.f;
        bf16* sAh = (bf16*)(sAall + tile*64*ASRQ);
        #pragma unroll
        for (int j = 0; j < 16; j++) {
            int d = d0 + j;
            float f = x0*W1[d] + x1*W1[DD+d] + x2*W1[2*DD+d] + b1[d];
            f = leaky(f*g1[d] + be1[d]);
            sAh[pt*(2*ASRQ) + d] = __float2bfloat16_rn(f);
            float hh = x0*Ws1[d] + x1*Ws1[DD+d] + x2*Ws1[2*DD+d] + bs1[d];
            hh = hh > 0.f ? hh : 0.f;
            s0 += hh*Ws2[d*LV+0]; s1 += hh*Ws2[d*LV+1]; s2 += hh*Ws2[d*LV+2];
        }
        s0 += __shfl_xor_sync(0xFFFFFFFF, s0, 1); s0 += __shfl_xor_sync(0xFFFFFFFF, s0, 2);
        s1 += __shfl_xor_sync(0xFFFFFFFF, s1, 1); s1 += __shfl_xor_sync(0xFFFFFFFF, s1, 2);
        s2 += __shfl_xor_sync(0xFFFFFFFF, s2, 1); s2 += __shfl_xor_sync(0xFFFFFFFF, s2, 2);
        if (q == 0) {
            g_fw[p*LV+0] = 1.f/(1.f + expf(-s0));
            g_fw[p*LV+1] = 1.f/(1.f + expf(-s1));
            g_fw[p*LV+2] = 1.f/(1.f + expf(-s2));
        }
        __syncthreads();

        const int w8 = (tid >> 5) & 7;
        const int lane = tid & 31, gid = lane >> 2, tig = lane & 3;
        const int wm = (w8 & 1)*32, wn = (w8 >> 1)*32;
        const uint32_t* sA = sAall + tile*64*ASRQ;
        float acc[2][4][4] = {};
        #pragma unroll
        for (int ks = 0; ks < 4; ks++) {
            const int ko = ks*8;
            uint32_t af[2][4], bfr[4][2];
            #pragma unroll
            for (int mf = 0; mf < 2; mf++) {
                const uint32_t* ap = sA + (wm + mf*16 + gid)*ASRQ + ko + tig;
                af[mf][0] = ap[0];
                af[mf][1] = ap[8*ASRQ];
                af[mf][2] = ap[4];
                af[mf][3] = ap[8*ASRQ + 4];
            }
            #pragma unroll
            for (int nf = 0; nf < 4; nf++) {
                const uint32_t* bp = sB + (wn + nf*8 + gid)*BSRQ + ko + tig;
                bfr[nf][0] = bp[0];
                bfr[nf][1] = bp[4];
            }
            #pragma unroll
            for (int mf = 0; mf < 2; mf++)
                #pragma unroll
                for (int nf = 0; nf < 4; nf++)
                    mma_bf16(acc[mf][nf], af[mf], bfr[nf]);
        }
        #pragma unroll
        for (int mf = 0; mf < 2; mf++) {
            const int row = m0 + wm + mf*16 + gid;
            #pragma unroll
            for (int nf = 0; nf < 4; nf++) {
                const int col = wn + nf*8 + tig*2;
                __nv_bfloat162 lo, hi;
                lo.x = __float2bfloat16_rn(acc[mf][nf][0]); lo.y = __float2bfloat16_rn(acc[mf][nf][1]);
                hi.x = __float2bfloat16_rn(acc[mf][nf][2]); hi.y = __float2bfloat16_rn(acc[mf][nf][3]);
                *(__nv_bfloat162*)(g_PQb + (size_t)row*128 + col)     = lo;
                *(__nv_bfloat162*)(g_PQb + (size_t)(row+8)*128 + col) = hi;
            }
        }
        return;
    }

    // ---- KNN: 4 sorted-adjacent queries/warp, circular scan of sorted array ----
    {
        float4* sc  = (float4*)fsm;               // sorted points [2048]
        int*    sid = (int*)(fsm + NN*16);        // original ids [2048]
        const int b  = bx >> 2;                   // 4 blocks per batch
        const int qb = (bx & 3) * 512;            // sorted-position base
        const int w = tid >> 5, lane = tid & 31;

        for (int i = tid; i < NN; i += 512) {
            sc[i]  = g_sorted[b*NN + i];
            sid[i] = g_sid[b*NN + i];
        }
        __syncthreads();

        const int qpos = qb + w*4;                // this warp's 4 sorted queries
        float4 A0 = sc[qpos+0], A1 = sc[qpos+1], A2 = sc[qpos+2], A3 = sc[qpos+3];
        const int o0 = sid[qpos+0], o1 = sid[qpos+1], o2 = sid[qpos+2], o3 = sid[qpos+3];
        A0.x = -A0.x; A0.y = -A0.y; A0.z = -A0.z;
        A1.x = -A1.x; A1.y = -A1.y; A1.z = -A1.z;
        A2.x = -A2.x; A2.y = -A2.y; A2.z = -A2.z;
        A3.x = -A3.x; A3.y = -A3.y; A3.z = -A3.z;

        const int grp = lane >> 3, gl = lane & 7;
        float slotD = FLT_MAX; int slotI = 0;
        float tau[4] = {FLT_MAX, FLT_MAX, FLT_MAX, FLT_MAX};
        const int startc = qpos >> 5;

        for (int cc = 0; cc < NN/32; cc++) {
            const int ch = (startc + cc) & (NN/32 - 1);
            float4 cd = sc[ch*32 + lane];
            float d[4];
            d[0] = fmaf(A0.x, cd.x, fmaf(A0.y, cd.y, fmaf(A0.z, cd.z, A0.w + cd.w)));
            d[1] = fmaf(A1.x, cd.x, fmaf(A1.y, cd.y, fmaf(A1.z, cd.z, A1.w + cd.w)));
            d[2] = fmaf(A2.x, cd.x, fmaf(A2.y, cd.y, fmaf(A2.z, cd.z, A2.w + cd.w)));
            d[3] = fmaf(A3.x, cd.x, fmaf(A3.y, cd.y, fmaf(A3.z, cd.z, A3.w + cd.w)));
            bool p0 = d[0] < tau[0], p1 = d[1] < tau[1];
            bool p2 = d[2] < tau[2], p3 = d[3] < tau[3];
            unsigned mAny = __ballot_sync(0xFFFFFFFFu, p0 | p1 | p2 | p3);
            if (!mAny) continue;     // warp-uniform

            int myIdx = sid[ch*32 + lane];
            unsigned m[4];
            m[0] = __ballot_sync(0xFFFFFFFFu, p0);
            m[1] = __ballot_sync(0xFFFFFFFFu, p1);
            m[2] = __ballot_sync(0xFFFFFFFFu, p2);
            m[3] = __ballot_sync(0xFFFFFFFFu, p3);
            #pragma unroll
            for (int q = 0; q < 4; q++) {
                unsigned mm = m[q];
                if (!mm) continue;   // warp-uniform
                while (mm) {
                    int src = __ffs(mm) - 1; mm &= mm - 1;
                    float cvf = __shfl_sync(0xFFFFFFFFu, d[q], src);
                    int cidx  = __shfl_sync(0xFFFFFFFFu, myIdx, src);
                    float prevD = __shfl_up_sync(0xFFFFFFFFu, slotD, 1);
                    int   prevI = __shfl_up_sync(0xFFFFFFFFu, slotI, 1);
                    if (grp == q) {
                        if (gl == 0) { prevD = cvf; prevI = cidx; }
                        if (slotD > cvf) {
                            bool pb = prevD > cvf;
                            slotD = pb ? prevD : cvf;
                            slotI = pb ? prevI : cidx;
                        }
                    }
                }
                tau[q] = __shfl_sync(0xFFFFFFFFu, slotD, q*8 + 7);
            }
        }
        int oq = (grp == 0) ? o0 : (grp == 1) ? o1 : (grp == 2) ? o2 : o3;
        g_idx[(b*NN + oq)*KNB + gl] = slotI;
    }
}

// ================= kernel 2 (tail): gather + GEMM1 + GEMM2 + out ==============
#define T_ASR 100
#define T_G1SR 132
#define T_A1 0
#define T_B1 12800
#define T_G1 38400
#define T_SMEM (55296*4)   // 221184 bytes

__global__ void __launch_bounds__(512)
k_tail(const float* __restrict__ b2, const float* __restrict__ g2,
       const float* __restrict__ be2,
       const float* __restrict__ bf1, const float* __restrict__ gf1,
       const float* __restrict__ bef1,
       const float* __restrict__ bf2, const float* __restrict__ gf2,
       const float* __restrict__ bef2,
       float* __restrict__ out, const float* __restrict__ x,
       const float* __restrict__ Wf3, const float* __restrict__ bf3)
{
    extern __shared__ uint32_t sm32[];
    __shared__ float sAcc[128][3];

    const int t = threadIdx.x, lane = t & 31, wid = t >> 5;
    const int gid = lane >> 2, tig = lane & 3;
    const int m0 = blockIdx.x * 128;
    const uint32_t sbase = smem_u32(sm32);

    #pragma unroll
    for (int it = 0; it < 12; it++) {
        int i = it*512 + t;
        int row = i/24, seg = i%24;
        CP_ASYNC16(sbase + (uint32_t)(T_B1*4 + row*400 + seg*16),
                   g_Bt1B + (size_t)row*192 + seg*8);
    }
    CP_COMMIT();

    {
        const int pt = t >> 2, q = t & 3, d0 = q*16;
        const int p = m0 + pt, b = p >> 11;

        float pv[16], gg[16], cc[16], m[16];
        uint4 pv0 = *(const uint4*)(g_PQb + (size_t)p*128 + d0);
        uint4 pv1 = *(const uint4*)(g_PQb + (size_t)p*128 + d0 + 8);
        #pragma unroll
        for (int j = 0; j < 8; j++) {
            pv[j]   = bf2f(((const uint32_t*)&pv0)[j>>1], j&1);
            pv[8+j] = bf2f(((const uint32_t*)&pv1)[j>>1], j&1);
        }
        #pragma unroll
        for (int j = 0; j < 16; j++) {
            gg[j] = g2[d0+j];
            cc[j] = b2[d0+j]*gg[j] + be2[d0+j];
            m[j] = -FLT_MAX;
        }
        int idx[KNB];
        *(int4*)&idx[0] = *(const int4*)(g_idx + p*KNB);
        *(int4*)&idx[4] = *(const int4*)(g_idx + p*KNB + 4);
        #pragma unroll
        for (int k = 0; k < KNB; k++) {
            const bf16* qrow = g_PQb + (size_t)(b*NN + idx[k])*128 + 64 + d0;
            uint4 qv0 = *(const uint4*)(qrow);
            uint4 qv1 = *(const uint4*)(qrow + 8);
            #pragma unroll
            for (int j = 0; j < 8; j++) {
                float qa = bf2f(((const uint32_t*)&qv0)[j>>1], j&1);
                float qb = bf2f(((const uint32_t*)&qv1)[j>>1], j&1);
                m[j]   = fmaxf(m[j],   leaky((pv[j]   + qa)*gg[j]   + cc[j]));
                m[8+j] = fmaxf(m[8+j], leaky((pv[8+j] + qb)*gg[8+j] + cc[8+j]));
            }
        }
        float f0 = g_fw[p*LV+0], f1 = g_fw[p*LV+1], f2 = g_fw[p*LV+2];
        bf16* sAh = (bf16*)(sm32 + T_A1);
        #pragma unroll
        for (int j = 0; j < 16; j++) {
            int d = d0 + j;
            sAh[pt*(2*T_ASR) + d]       = __float2bfloat16_rn(m[j]*f0);
            sAh[pt*(2*T_ASR) + 64 + d]  = __float2bfloat16_rn(m[j]*f1);
            sAh[pt*(2*T_ASR) + 128 + d] = __float2bfloat16_rn(m[j]*f2);
        }
    }
    if (t < 384) sAcc[t/3][t%3] = 0.f;
    CP_WAIT(0);
    __syncthreads();

    const int wm = (wid & 3)*32;
    {
        const int wn1 = (wid >> 2)*64;
        float acc1[2][8][4] = {};
        #pragma unroll
        for (int ks = 0; ks < 12; ks++) {
            const int ko = ks*8;
            uint32_t af[2][4], bfr[8][2];
            #pragma unroll
            for (int mf = 0; mf < 2; mf++) {
                const uint32_t* ap = sm32 + T_A1 + (wm + mf*16 + gid)*T_ASR + ko + tig;
                af[mf][0] = ap[0];
                af[mf][1] = ap[8*T_ASR];
                af[mf][2] = ap[4];
                af[mf][3] = ap[8*T_ASR + 4];
            }
            #pragma unroll
            for (int nf = 0; nf < 8; nf++) {
                const uint32_t* bp = sm32 + T_B1 + (wn1 + nf*8 + gid)*T_ASR + ko + tig;
                bfr[nf][0] = bp[0];
                bfr[nf][1] = bp[4];
            }
            #pragma unroll
            for (int mf = 0; mf < 2; mf++)
                #pragma unroll
                for (int nf = 0; nf < 8; nf++)
                    mma_bf16(acc1[mf][nf], af[mf], bfr[nf]);
        }
        #pragma unroll
        for (int mf = 0; mf < 2; mf++) {
            const int rl = wm + mf*16 + gid;
            #pragma unroll
            for (int nf = 0; nf < 8; nf++) {
                const int col = wn1 + nf*8 + tig*2;
                float e0 = __ldg(bf1+col),  e1 = __ldg(bf1+col+1);
                float q0 = __ldg(gf1+col),  q1 = __ldg(gf1+col+1);
                float h0 = __ldg(bef1+col), h1 = __ldg(bef1+col+1);
                float v0 = leaky((acc1[mf][nf][0] + e0)*q0 + h0);
                float v1 = leaky((acc1[mf][nf][1] + e1)*q1 + h1);
                float v2 = leaky((acc1[mf][nf][2] + e0)*q0 + h0);
                float v3 = leaky((acc1[mf][nf][3] + e1)*q1 + h1);
                __nv_bfloat162 lo, hi;
                lo.x = __float2bfloat16_rn(v0); lo.y = __float2bfloat16_rn(v1);
                hi.x = __float2bfloat16_rn(v2); hi.y = __float2bfloat16_rn(v3);
                sm32[T_G1 + rl*T_G1SR + (col>>1)]     = *(uint32_t*)&lo;
                sm32[T_G1 + (rl+8)*T_G1SR + (col>>1)] = *(uint32_t*)&hi;
            }
        }
    }
    __syncthreads();

    #pragma unroll
    for (int it = 0; it < 8; it++) {
        int i = it*512 + t;
        int row = i >> 5, seg = i & 31;
        CP_ASYNC16(sbase + (uint32_t)(T_B1*4 + row*528 + seg*16),
                   g_Bt2B + (size_t)row*256 + seg*8);
    }
    CP_COMMIT();
    CP_WAIT(0);
    __syncthreads();

    {
        const int wn2 = (wid >> 2)*32;
        float acc2[2][4][4] = {};
        #pragma unroll
        for (int ks = 0; ks < 16; ks++) {
            const int ko = ks*8;
            uint32_t af[2][4], bfr[4][2];
            #pragma unroll
            for (int mf = 0; mf < 2; mf++) {
                const uint32_t* ap = sm32 + T_G1 + (wm + mf*16 + gid)*T_G1SR + ko + tig;
                af[mf][0] = ap[0];
                af[mf][1] = ap[8*T_G1SR];
                af[mf][2] = ap[4];
                af[mf][3] = ap[8*T_G1SR + 4];
            }
            #pragma unroll
            for (int nf = 0; nf < 4; nf++) {
                const uint32_t* bp = sm32 + T_B1 + (wn2 + nf*8 + gid)*T_G1SR + ko + tig;
                bfr[nf][0] = bp[0];
                bfr[nf][1] = bp[4];
            }
            #pragma unroll
            for (int mf = 0; mf < 2; mf++)
                #pragma unroll
                for (int nf = 0; nf < 4; nf++)
                    mma_bf16(acc2[mf][nf], af[mf], bfr[nf]);
        }

        #pragma unroll
        for (int mf = 0; mf < 2; mf++) {
            float sLo[3] = {0.f,0.f,0.f}, sHi[3] = {0.f,0.f,0.f};
            #pragma unroll
            for (int nf = 0; nf < 4; nf++) {
                const int col = wn2 + nf*8 + tig*2;
                float e0 = __ldg(bf2+col),  e1 = __ldg(bf2+col+1);
                float q0 = __ldg(gf2+col),  q1 = __ldg(gf2+col+1);
                float h0 = __ldg(bef2+col), h1 = __ldg(bef2+col+1);
                float v0 = leaky((acc2[mf][nf][0] + e0)*q0 + h0);
                float v1 = leaky((acc2[mf][nf][1] + e1)*q1 + h1);
                float v2 = leaky((acc2[mf][nf][2] + e0)*q0 + h0);
                float v3 = leaky((acc2[mf][nf][3] + e1)*q1 + h1);
                #pragma unroll
                for (int j = 0; j < 3; j++) {
                    float w0 = __ldg(Wf3 + col*3 + j);
                    float w1 = __ldg(Wf3 + (col+1)*3 + j);
                    sLo[j] += v0*w0 + v1*w1;
                    sHi[j] += v2*w0 + v3*w1;
                }
            }
            #pragma unroll
            for (int j = 0; j < 3; j++) {
                sLo[j] += __shfl_xor_sync(0xFFFFFFFF, sLo[j], 1);
                sLo[j] += __shfl_xor_sync(0xFFFFFFFF, sLo[j], 2);
                sHi[j] += __shfl_xor_sync(0xFFFFFFFF, sHi[j], 1);
                sHi[j] += __shfl_xor_sync(0xFFFFFFFF, sHi[j], 2);
            }
            if (tig == 0) {
                int rl = wm + mf*16 + gid;
                #pragma unroll
                for (int j = 0; j < 3; j++) {
                    atomicAdd(&sAcc[rl][j],     sLo[j]);
                    atomicAdd(&sAcc[rl + 8][j], sHi[j]);
                }
            }
        }
    }

    __syncthreads();
    if (t < 128) {
        int p = m0 + t;
        #pragma unroll
        for (int j = 0; j < 3; j++)
            out[p*3+j] = x[p*3+j] + 0.1f*(sAcc[t][j] + __ldg(bf3+j));
    }
}

// ---------------- launch -------------------------------------------------------
extern "C" void kernel_launch(void* const* d_in, const int* in_sizes, int n_in,
                              void* d_out, int out_size)
{
    const float* x   = (const float*)d_in[0];
    const float* W1  = (const float*)d_in[1];
    const float* b1  = (const float*)d_in[2];
    const float* g1  = (const float*)d_in[3];
    const float* be1 = (const float*)d_in[4];
    const float* W2  = (const float*)d_in[5];
    const float* b2  = (const float*)d_in[6];
    const float* g2  = (const float*)d_in[7];
    const float* be2 = (const float*)d_in[8];
    const float* Ws1 = (const float*)d_in[9];
    const float* bs1 = (const float*)d_in[10];
    const float* Ws2 = (const float*)d_in[11];
    const float* bs2 = (const float*)d_in[12];
    const float* Wf1 = (const float*)d_in[13];
    const float* bf1 = (const float*)d_in[14];
    const float* gf1 = (const float*)d_in[15];
    const float* bef1= (const float*)d_in[16];
    const float* Wf2 = (const float*)d_in[17];
    const float* bf2 = (const float*)d_in[18];
    const float* gf2 = (const float*)d_in[19];
    const float* bef2= (const float*)d_in[20];
    const float* Wf3 = (const float*)d_in[21];
    const float* bf3 = (const float*)d_in[22];
    float* out = (float*)d_out;

    cudaFuncSetAttribute(k_front, cudaFuncAttributeMaxDynamicSharedMemorySize, FRONT_SMEM);
    cudaFuncSetAttribute(k_tail,  cudaFuncAttributeMaxDynamicSharedMemorySize, T_SMEM);

    // 0. counting sort into cell order (8 blocks, static smem)
    k_grid<<<BB, 1024>>>(x);

    // 1. sorted-KNN (32 blk) || feature+PQ (128 blk) || weight prep (24 blk)
    k_front<<<32 + 128 + 24, 512, FRONT_SMEM>>>(
        x, W1, b1, g1, be1, Ws1, bs1, Ws2, bs2, W2, Wf1, Wf2);

    // 2. gather + fusion1 + fusion2 + projection + residual, fully fused
    k_tail<<<NP/128, 512, T_SMEM>>>(b2, g2, be2, bf1, gf1, bef1,
                                    bf2, gf2, bef2, out, x, Wf3, bf3);
}